// round 4
// baseline (speedup 1.0000x reference)
#include <cuda_runtime.h>
#include <cstdint>

// Problem constants
#define BATCH 512
#define INF   4096
#define OUTF  4096

// GEMM tiling: CTA 128x128, K-chunk 32 fp32. Warp grid 2(M) x 4(N), warp tile 64x32.
#define TM 128
#define TN 128
#define KC 32
#define ITERS (INF / KC)          // 128
#define STAGES 4
#define AS_STRIDE 36              // 32 + 4 pad floats -> conflict-free LDSM row pointers
#define TILE_FLOATS (128 * AS_STRIDE)           // 4608 floats = 18432 B
#define STAGE_BYTES (2 * TILE_FLOATS * 4)       // A + B = 36864 B
#define SMEM_BYTES (STAGES * STAGE_BYTES)       // 147456 B

// Scratch (device globals are the sanctioned scratch mechanism)
__device__ float g_W[(size_t)OUTF * INF];   // dequantized weight, tf32-rounded (64 MB)
__device__ float g_x[(size_t)BATCH * INF];  // x, tf32-rounded (8 MB)

// ---------------- PTX helpers (plain-sm_103 legal) ----------------
__device__ __forceinline__ uint32_t smem_u32(const void* p) {
    uint32_t a;
    asm("{ .reg .u64 t; cvta.to.shared.u64 t, %1; cvt.u32.u64 %0, t; }" : "=r"(a) : "l"(p));
    return a;
}

#define CP_ASYNC16(dst_smem, src_gmem) \
    asm volatile("cp.async.cg.shared.global [%0], [%1], 16;" \
                 :: "r"((uint32_t)(dst_smem)), "l"(src_gmem) : "memory")
#define CP_COMMIT() asm volatile("cp.async.commit_group;" ::: "memory")
#define CP_WAIT(n)  asm volatile("cp.async.wait_group %0;" :: "n"(n) : "memory")

// ldmatrix x4 (b16 view; one fp32 per lane per 8x4-fp32 tile)
#define LDSM_X4(r0, r1, r2, r3, addr) \
    asm volatile("ldmatrix.sync.aligned.m8n8.x4.shared.b16 {%0,%1,%2,%3}, [%4];" \
                 : "=r"(r0), "=r"(r1), "=r"(r2), "=r"(r3) : "r"(addr))

// mma.sync m16n8k8 tf32 (sm_80+ baseline)
#define MMA_TF32(d, a, b) \
    asm volatile( \
        "mma.sync.aligned.m16n8k8.row.col.f32.tf32.tf32.f32 " \
        "{%0,%1,%2,%3}, {%4,%5,%6,%7}, {%8,%9}, {%0,%1,%2,%3};" \
        : "+f"((d)[0]), "+f"((d)[1]), "+f"((d)[2]), "+f"((d)[3]) \
        : "r"((a)[0]), "r"((a)[1]), "r"((a)[2]), "r"((a)[3]), \
          "r"((b)[0]), "r"((b)[1]))

__device__ __forceinline__ float tf32_rn(float x) {
    uint32_t b;
    asm("cvt.rna.tf32.f32 %0, %1;" : "=r"(b) : "f"(x));
    return __uint_as_float(b);
}

__device__ __forceinline__ float scale_from_exponent(const int* e) {
    int iv = *e;
    if (iv > -1000000 && iv < 1000000) return exp2f((float)iv);
    return exp2f(__int_as_float(iv));
}

// ---------------- kernel 1: dequant W = (U @ t_hat), tf32-rounded ----------------
__global__ void __launch_bounds__(256) prep_w_kernel(
    const float4* __restrict__ U4, const float* __restrict__ q, const int* __restrict__ e)
{
    float sc = scale_from_exponent(e) * (1.0f / 7.0f);
    float t0 = q[0] * sc, t1 = q[1] * sc, t2 = q[2] * sc, t3 = q[3] * sc;

    size_t t = (size_t)blockIdx.x * 256 + threadIdx.x;
    const float4* u = U4 + (t << 2);
    float4 a = u[0], b = u[1], c = u[2], d = u[3];
    float4 r;
    r.x = tf32_rn(fmaf(a.x, t0, fmaf(a.y, t1, fmaf(a.z, t2, a.w * t3))));
    r.y = tf32_rn(fmaf(b.x, t0, fmaf(b.y, t1, fmaf(b.z, t2, b.w * t3))));
    r.z = tf32_rn(fmaf(c.x, t0, fmaf(c.y, t1, fmaf(c.z, t2, c.w * t3))));
    r.w = tf32_rn(fmaf(d.x, t0, fmaf(d.y, t1, fmaf(d.z, t2, d.w * t3))));
    reinterpret_cast<float4*>(g_W)[t] = r;
}

// ---------------- kernel 2: round x to tf32 ----------------
__global__ void __launch_bounds__(256) round_x_kernel(const float4* __restrict__ x4)
{
    size_t i = (size_t)blockIdx.x * 256 + threadIdx.x;
    float4 v = x4[i];
    v.x = tf32_rn(v.x); v.y = tf32_rn(v.y); v.z = tf32_rn(v.z); v.w = tf32_rn(v.w);
    reinterpret_cast<float4*>(g_x)[i] = v;
}

// ---------------- kernel 3: tf32 mma.sync GEMM: y = x @ W^T + b ----------------
__global__ void __launch_bounds__(256, 1) gemm_tf32_kernel(
    const float* __restrict__ bias, float* __restrict__ out)
{
    extern __shared__ float smf[];
    const uint32_t sb = smem_u32(smf);
    const int tid  = threadIdx.x;
    const int wid  = tid >> 5;
    const int lane = tid & 31;
    const int g    = lane >> 2;       // groupID
    const int t    = lane & 3;        // thread-in-group
    const int wrow = wid >> 2;        // 0..1 (M)
    const int wcol = wid & 3;         // 0..3 (N)
    const int m0 = blockIdx.y * TM;
    const int n0 = blockIdx.x * TN;

    const float* Ag = g_x + (size_t)m0 * INF;
    const float* Bg = g_W + (size_t)n0 * INF;

    float acc[4][4][4];
    #pragma unroll
    for (int i = 0; i < 4; ++i)
        #pragma unroll
        for (int j = 0; j < 4; ++j)
            #pragma unroll
            for (int k = 0; k < 4; ++k) acc[i][j][k] = 0.f;

    auto load_stage = [&](int it, int s) {
        const uint32_t As = sb + (uint32_t)s * STAGE_BYTES;
        const uint32_t Bs = As + TILE_FLOATS * 4;
        const int kbase = it * KC;
        #pragma unroll
        for (int i = 0; i < 4; ++i) {
            int cid = i * 256 + tid;
            int r = cid >> 3, c = cid & 7;
            CP_ASYNC16(As + (uint32_t)(r * AS_STRIDE + c * 4) * 4,
                       Ag + (size_t)r * INF + kbase + c * 4);
        }
        #pragma unroll
        for (int i = 0; i < 4; ++i) {
            int cid = i * 256 + tid;
            int r = cid >> 3, c = cid & 7;
            CP_ASYNC16(Bs + (uint32_t)(r * AS_STRIDE + c * 4) * 4,
                       Bg + (size_t)r * INF + kbase + c * 4);
        }
        CP_COMMIT();
    };

    #pragma unroll
    for (int s = 0; s < STAGES - 1; ++s) load_stage(s, s);

    // ldmatrix per-lane row/col offset pattern:
    //   lanes 0-15  -> rows rowbase + (lane&15), k-offset +0
    //   lanes 16-31 -> rows rowbase + (lane&15), k-offset +4
    const int lrow  = lane & 15;
    const int lkoff = (lane >> 4) << 2;
    // float-index offsets (before *4 bytes), k0 added per ks
    const uint32_t a_lane_off = (uint32_t)((wrow * 64 + lrow) * AS_STRIDE + lkoff) * 4;
    const uint32_t b_lane_off = (uint32_t)((wcol * 32 + lrow) * AS_STRIDE + lkoff) * 4;

    #pragma unroll 1
    for (int it = 0; it < ITERS; ++it) {
        CP_WAIT(STAGES - 2);
        __syncthreads();
        int nxt = it + STAGES - 1;
        if (nxt < ITERS) load_stage(nxt, nxt % STAGES);

        const uint32_t As = sb + (uint32_t)(it % STAGES) * STAGE_BYTES;
        const uint32_t Bs = As + TILE_FLOATS * 4;

        #pragma unroll
        for (int ks = 0; ks < 4; ++ks) {
            const uint32_t k0b = (uint32_t)(ks * 8) * 4;
            uint32_t a[4][4], b[4][2];
            #pragma unroll
            for (int mt = 0; mt < 4; ++mt) {
                // x4 tiles: (row, k0), (row+8, k0), (row, k0+4), (row+8, k0+4)
                LDSM_X4(a[mt][0], a[mt][1], a[mt][2], a[mt][3],
                        As + a_lane_off + (uint32_t)(mt * 16 * AS_STRIDE) * 4 + k0b);
            }
            #pragma unroll
            for (int np = 0; np < 2; ++np) {
                // x4 tiles: (n, k0), (n+8, k0), (n, k0+4), (n+8, k0+4)
                //  -> r0 = b[2np][0], r1 = b[2np+1][0], r2 = b[2np][1], r3 = b[2np+1][1]
                LDSM_X4(b[2 * np][0], b[2 * np + 1][0], b[2 * np][1], b[2 * np + 1][1],
                        Bs + b_lane_off + (uint32_t)(np * 16 * AS_STRIDE) * 4 + k0b);
            }
            #pragma unroll
            for (int mt = 0; mt < 4; ++mt)
                #pragma unroll
                for (int nt = 0; nt < 4; ++nt)
                    MMA_TF32(acc[mt][nt], a[mt], b[nt]);
        }
    }

    // ---- epilogue: registers -> gmem with fused bias, float2 stores ----
    #pragma unroll
    for (int nt = 0; nt < 4; ++nt) {
        const int n = n0 + wcol * 32 + nt * 8 + 2 * t;
        const float b0 = bias[n], b1 = bias[n + 1];
        #pragma unroll
        for (int mt = 0; mt < 4; ++mt) {
            const int m = m0 + wrow * 64 + mt * 16 + g;
            float2 lo = make_float2(acc[mt][nt][0] + b0, acc[mt][nt][1] + b1);
            float2 hi = make_float2(acc[mt][nt][2] + b0, acc[mt][nt][3] + b1);
            *reinterpret_cast<float2*>(out + (size_t)m * OUTF + n) = lo;
            *reinterpret_cast<float2*>(out + (size_t)(m + 8) * OUTF + n) = hi;
        }
    }
}

// ---------------- launch ----------------
extern "C" void kernel_launch(void* const* d_in, const int* in_sizes, int n_in,
                              void* d_out, int out_size)
{
    const float* x = (const float*)d_in[0];   // [512, 4096]
    const float* U = (const float*)d_in[1];   // [4096*4096, 4]
    const float* q = (const float*)d_in[2];   // [4]
    const float* b = (const float*)d_in[3];   // [4096]
    const int*   e = (const int*)d_in[4];     // exponent scalar

    cudaFuncSetAttribute(gemm_tf32_kernel,
                         cudaFuncAttributeMaxDynamicSharedMemorySize, SMEM_BYTES);

    prep_w_kernel<<<16384, 256>>>((const float4*)U, q, e);
    round_x_kernel<<<2048, 256>>>((const float4*)x);
    gemm_tf32_kernel<<<dim3(OUTF / TN, BATCH / TM), 256, SMEM_BYTES>>>(b, (float*)d_out);
}